// round 2
// baseline (speedup 1.0000x reference)
#include <cuda_runtime.h>
#include <float.h>

#define L_SEQ 4096
#define N_TOTAL 512
#define WPB 8   // warps (= kernels) per block

__device__ int g_inv[N_TOTAL];
__device__ int g_P;

// Build inverse permutation and recover P from group-0 metadata.
__global__ void setup_kernel(const int* __restrict__ perm,
                             const int* __restrict__ off0,
                             const int* __restrict__ lout0,
                             int n_perm) {
    int j = threadIdx.x;
    if (j < n_perm) g_inv[perm[j]] = j;
    if (j == 0) {
        // ks=7 group: off0[6]-off0[0] = 6*d ; lout = L + 2*pad - 6*d
        int d6  = off0[6] - off0[0];
        int pad = (lout0[0] - L_SEQ + d6) / 2;
        g_P = off0[0] + pad;
    }
}

template<int KS>
__device__ __forceinline__ void run_group(
    const float* __restrict__ sx,
    const float* __restrict__ w, const float* __restrict__ bias,
    const int*  __restrict__ off, const int* __restrict__ lout,
    float* __restrict__ out, int gi, int base, int b, int stride)
{
    const int lane = threadIdx.x & 31;
    const int P = g_P;

    float wk[KS];
    int   ck[KS];
#pragma unroll
    for (int k = 0; k < KS; k++) {
        wk[k] = __ldg(&w[gi * KS + k]);
        ck[k] = __ldg(&off[gi * KS + k]) - P;   // x index = ck[k] + t, zero if OOB
    }
    const float bsv = __ldg(&bias[gi]);
    const int   lo  = __ldg(&lout[gi]);

    float mx  = -FLT_MAX;
    int   cnt = 0;

    int t = lane;
    // unroll-by-2 main loop (two t per lane per iteration)
    for (; t + 32 < lo; t += 64) {
        float s0 = bsv, s1 = bsv;
#pragma unroll
        for (int k = 0; k < KS; k++) {
            int j0 = ck[k] + t;
            int j1 = j0 + 32;
            float v0 = ((unsigned)j0 < (unsigned)L_SEQ) ? sx[j0] : 0.0f;
            float v1 = ((unsigned)j1 < (unsigned)L_SEQ) ? sx[j1] : 0.0f;
            s0 = fmaf(wk[k], v0, s0);
            s1 = fmaf(wk[k], v1, s1);
        }
        mx = fmaxf(mx, fmaxf(s0, s1));
        cnt += (s0 > 0.0f);
        cnt += (s1 > 0.0f);
    }
    // remainder
    for (; t < lo; t += 32) {
        float s = bsv;
#pragma unroll
        for (int k = 0; k < KS; k++) {
            int j = ck[k] + t;
            float v = ((unsigned)j < (unsigned)L_SEQ) ? sx[j] : 0.0f;
            s = fmaf(wk[k], v, s);
        }
        mx = fmaxf(mx, s);
        cnt += (s > 0.0f);
    }

    // warp reductions
#pragma unroll
    for (int o = 16; o; o >>= 1) {
        mx   = fmaxf(mx, __shfl_xor_sync(0xffffffffu, mx, o));
        cnt += __shfl_xor_sync(0xffffffffu, cnt, o);
    }

    if (lane == 0) {
        int col = g_inv[base + gi];
        out[b * stride + 2 * col]     = mx;
        out[b * stride + 2 * col + 1] = (float)cnt / (float)lo;
    }
}

__global__ __launch_bounds__(WPB * 32)
void rocket_all_kernel(
    const float* __restrict__ x,
    const float* __restrict__ w0, const float* __restrict__ b0,
    const int*  __restrict__ off0, const int* __restrict__ lout0, int n0,
    const float* __restrict__ w1, const float* __restrict__ b1,
    const int*  __restrict__ off1, const int* __restrict__ lout1, int n1,
    const float* __restrict__ w2, const float* __restrict__ b2,
    const int*  __restrict__ off2, const int* __restrict__ lout2, int n2,
    float* __restrict__ out, int nb0, int nb1, int stride)
{
    __shared__ float sx[L_SEQ];
    const int b = blockIdx.y;
    const float* xb = x + (size_t)b * L_SEQ;

    // stage x[b] into shared memory, vectorized
    for (int i = threadIdx.x; i < L_SEQ / 4; i += blockDim.x)
        ((float4*)sx)[i] = ((const float4*)xb)[i];
    __syncthreads();

    const int warp = threadIdx.x >> 5;
    const int bx = blockIdx.x;

    if (bx < nb0) {
        int gi = bx * WPB + warp;
        if (gi < n0) run_group<7>(sx, w0, b0, off0, lout0, out, gi, 0, b, stride);
    } else if (bx < nb0 + nb1) {
        int gi = (bx - nb0) * WPB + warp;
        if (gi < n1) run_group<9>(sx, w1, b1, off1, lout1, out, gi, n0, b, stride);
    } else {
        int gi = (bx - nb0 - nb1) * WPB + warp;
        if (gi < n2) run_group<11>(sx, w2, b2, off2, lout2, out, gi, n0 + n1, b, stride);
    }
}

extern "C" void kernel_launch(void* const* d_in, const int* in_sizes, int n_in,
                              void* d_out, int out_size) {
    // Two possible input orderings; disambiguate via sizes.
    // Dict order:      x, perm, P, w0,b0,off0,lout0, w1,b1,off1,lout1, w2,b2,off2,lout2
    // Signature order: x, w0,b0,off0,lout0, w1,b1,off1,lout1, w2,b2,off2,lout2, perm, P
    int ix, iperm, ig0, ig1, ig2;
    if (n_in >= 3 && in_sizes[1] == N_TOTAL && in_sizes[2] == 1) {
        ix = 0; iperm = 1; ig0 = 3; ig1 = 7; ig2 = 11;          // dict order
    } else {
        ix = 0; ig0 = 1; ig1 = 5; ig2 = 9; iperm = 13;          // signature order
    }

    const float* x     = (const float*)d_in[ix];
    const int*   perm  = (const int*)  d_in[iperm];

    const float* w0    = (const float*)d_in[ig0 + 0];
    const float* b0    = (const float*)d_in[ig0 + 1];
    const int*   off0  = (const int*)  d_in[ig0 + 2];
    const int*   lout0 = (const int*)  d_in[ig0 + 3];
    const float* w1    = (const float*)d_in[ig1 + 0];
    const float* b1    = (const float*)d_in[ig1 + 1];
    const int*   off1  = (const int*)  d_in[ig1 + 2];
    const int*   lout1 = (const int*)  d_in[ig1 + 3];
    const float* w2    = (const float*)d_in[ig2 + 0];
    const float* b2    = (const float*)d_in[ig2 + 1];
    const int*   off2  = (const int*)  d_in[ig2 + 2];
    const int*   lout2 = (const int*)  d_in[ig2 + 3];

    const int n0 = in_sizes[ig0 + 1];
    const int n1 = in_sizes[ig1 + 1];
    const int n2 = in_sizes[ig2 + 1];
    const int B  = in_sizes[ix] / L_SEQ;
    const int N  = n0 + n1 + n2;
    const int stride = 2 * N;

    setup_kernel<<<1, N_TOTAL>>>(perm, off0, lout0, in_sizes[iperm]);

    const int nb0 = (n0 + WPB - 1) / WPB;
    const int nb1 = (n1 + WPB - 1) / WPB;
    const int nb2 = (n2 + WPB - 1) / WPB;

    dim3 grid(nb0 + nb1 + nb2, B);
    rocket_all_kernel<<<grid, WPB * 32>>>(
        x,
        w0, b0, off0, lout0, n0,
        w1, b1, off1, lout1, n1,
        w2, b2, off2, lout2, n2,
        (float*)d_out, nb0, nb1, stride);
}

// round 3
// speedup vs baseline: 1.4615x; 1.4615x over previous
#include <cuda_runtime.h>
#include <float.h>

#define L_SEQ 4096
#define N_TOTAL 512
#define WPB 8            // warps (= kernels) per block
#define PAD_MAX 4096     // P <= 4094; padded length <= 4096 + 2*4094 = 12284 <= 12288
#define LP_MAX (L_SEQ + 2 * PAD_MAX)   // 12288 floats = 48KB static shared (exact limit)

__device__ int g_inv[N_TOTAL];
__device__ int g_P;

// Build inverse permutation and recover P from group-0 metadata.
__global__ void setup_kernel(const int* __restrict__ perm,
                             const int* __restrict__ off0,
                             const int* __restrict__ lout0,
                             int n_perm) {
    int j = threadIdx.x;
    if (j < n_perm) g_inv[perm[j]] = j;
    if (j == 0) {
        // ks=7 group: off0[6]-off0[0] = 6*d ; lout = L + 2*pad - 6*d
        int d6  = off0[6] - off0[0];
        int pad = (lout0[0] - L_SEQ + d6) / 2;
        g_P = off0[0] + pad;
    }
}

template<int KS>
__device__ __forceinline__ void run_group(
    const float* __restrict__ sx,          // zero-padded: x lives at [P, P+L)
    const float* __restrict__ w, const float* __restrict__ bias,
    const int*  __restrict__ off, const int* __restrict__ lout,
    float* __restrict__ out, int gi, int base, int b, int stride)
{
    const int lane = threadIdx.x & 31;

    float wk[KS];
    const float* pk[KS];
#pragma unroll
    for (int k = 0; k < KS; k++) {
        wk[k] = __ldg(&w[gi * KS + k]);
        pk[k] = sx + __ldg(&off[gi * KS + k]);   // index directly by t; never OOB
    }
    const float bsv = __ldg(&bias[gi]);
    const int   lo  = __ldg(&lout[gi]);

    float mx  = -FLT_MAX;
    int   cnt = 0;

    int t = lane;
    // unroll-by-2 main loop: two t per lane per iteration, no bounds checks at all
    for (; t + 32 < lo; t += 64) {
        float s0 = bsv, s1 = bsv;
#pragma unroll
        for (int k = 0; k < KS; k++) {
            s0 = fmaf(wk[k], pk[k][t],      s0);
            s1 = fmaf(wk[k], pk[k][t + 32], s1);
        }
        mx = fmaxf(mx, fmaxf(s0, s1));
        cnt += (s0 > 0.0f);
        cnt += (s1 > 0.0f);
    }
    // remainder (still no bounds checks — padded array covers all valid t)
    for (; t < lo; t += 32) {
        float s = bsv;
#pragma unroll
        for (int k = 0; k < KS; k++)
            s = fmaf(wk[k], pk[k][t], s);
        mx = fmaxf(mx, s);
        cnt += (s > 0.0f);
    }

    // warp reductions
#pragma unroll
    for (int o = 16; o; o >>= 1) {
        mx   = fmaxf(mx, __shfl_xor_sync(0xffffffffu, mx, o));
        cnt += __shfl_xor_sync(0xffffffffu, cnt, o);
    }

    if (lane == 0) {
        int col = g_inv[base + gi];
        out[b * stride + 2 * col]     = mx;
        out[b * stride + 2 * col + 1] = (float)cnt / (float)lo;
    }
}

__global__ __launch_bounds__(WPB * 32, 4)
void rocket_all_kernel(
    const float* __restrict__ x,
    const float* __restrict__ w0, const float* __restrict__ b0,
    const int*  __restrict__ off0, const int* __restrict__ lout0, int n0,
    const float* __restrict__ w1, const float* __restrict__ b1,
    const int*  __restrict__ off1, const int* __restrict__ lout1, int n1,
    const float* __restrict__ w2, const float* __restrict__ b2,
    const int*  __restrict__ off2, const int* __restrict__ lout2, int n2,
    float* __restrict__ out, int nb0, int nb1, int stride)
{
    __shared__ float sx[LP_MAX];
    const int b = blockIdx.y;
    const int P = g_P;

    // zero only the pad regions [0,P) and [P+L, P+L+P) — disjoint from the copy
    for (int i = threadIdx.x; i < P; i += WPB * 32) {
        sx[i]             = 0.0f;
        sx[P + L_SEQ + i] = 0.0f;
    }
    // stage x[b] into sx[P .. P+L): P is even (pads are 2*p0), so float2-aligned
    {
        const float2* xb2 = (const float2*)(x + (size_t)b * L_SEQ);
        float2* dst = (float2*)(sx + P);
        for (int i = threadIdx.x; i < L_SEQ / 2; i += WPB * 32)
            dst[i] = xb2[i];
    }
    __syncthreads();

    const int warp = threadIdx.x >> 5;
    const int bx = blockIdx.x;

    if (bx < nb0) {
        int gi = bx * WPB + warp;
        if (gi < n0) run_group<7>(sx, w0, b0, off0, lout0, out, gi, 0, b, stride);
    } else if (bx < nb0 + nb1) {
        int gi = (bx - nb0) * WPB + warp;
        if (gi < n1) run_group<9>(sx, w1, b1, off1, lout1, out, gi, n0, b, stride);
    } else {
        int gi = (bx - nb0 - nb1) * WPB + warp;
        if (gi < n2) run_group<11>(sx, w2, b2, off2, lout2, out, gi, n0 + n1, b, stride);
    }
}

extern "C" void kernel_launch(void* const* d_in, const int* in_sizes, int n_in,
                              void* d_out, int out_size) {
    // Two possible input orderings; disambiguate via sizes.
    // Dict order:      x, perm, P, w0,b0,off0,lout0, w1,b1,off1,lout1, w2,b2,off2,lout2
    // Signature order: x, w0,b0,off0,lout0, w1,b1,off1,lout1, w2,b2,off2,lout2, perm, P
    int ix, iperm, ig0, ig1, ig2;
    if (n_in >= 3 && in_sizes[1] == N_TOTAL && in_sizes[2] == 1) {
        ix = 0; iperm = 1; ig0 = 3; ig1 = 7; ig2 = 11;          // dict order
    } else {
        ix = 0; ig0 = 1; ig1 = 5; ig2 = 9; iperm = 13;          // signature order
    }

    const float* x     = (const float*)d_in[ix];
    const int*   perm  = (const int*)  d_in[iperm];

    const float* w0    = (const float*)d_in[ig0 + 0];
    const float* b0    = (const float*)d_in[ig0 + 1];
    const int*   off0  = (const int*)  d_in[ig0 + 2];
    const int*   lout0 = (const int*)  d_in[ig0 + 3];
    const float* w1    = (const float*)d_in[ig1 + 0];
    const float* b1    = (const float*)d_in[ig1 + 1];
    const int*   off1  = (const int*)  d_in[ig1 + 2];
    const int*   lout1 = (const int*)  d_in[ig1 + 3];
    const float* w2    = (const float*)d_in[ig2 + 0];
    const float* b2    = (const float*)d_in[ig2 + 1];
    const int*   off2  = (const int*)  d_in[ig2 + 2];
    const int*   lout2 = (const int*)  d_in[ig2 + 3];

    const int n0 = in_sizes[ig0 + 1];
    const int n1 = in_sizes[ig1 + 1];
    const int n2 = in_sizes[ig2 + 1];
    const int B  = in_sizes[ix] / L_SEQ;
    const int N  = n0 + n1 + n2;
    const int stride = 2 * N;

    setup_kernel<<<1, N_TOTAL>>>(perm, off0, lout0, in_sizes[iperm]);

    const int nb0 = (n0 + WPB - 1) / WPB;
    const int nb1 = (n1 + WPB - 1) / WPB;
    const int nb2 = (n2 + WPB - 1) / WPB;

    dim3 grid(nb0 + nb1 + nb2, B);
    rocket_all_kernel<<<grid, WPB * 32>>>(
        x,
        w0, b0, off0, lout0, n0,
        w1, b1, off1, lout1, n1,
        w2, b2, off2, lout2, n2,
        (float*)d_out, nb0, nb1, stride);
}